// round 16
// baseline (speedup 1.0000x reference)
#include <cuda_runtime.h>
#include <math.h>

#define HID 128
#define NEG 0.2f
#define MAXN 50000
#define MAXE 800000
#define MAXT (MAXE + MAXN)

typedef unsigned long long ull;

// ---------------- static scratch (no allocations allowed) ----------------
__device__ float g_h  [MAXN * HID];
__device__ float g_xl [MAXN * HID];
__device__ float g_xr [MAXN * HID];
__device__ float g_loop[MAXN * 32];
__device__ float g_ez  [MAXT];     // indexed by CSR position
__device__ int4  g_pack[MAXT];     // {eid, src, dst, 0} per CSR position
__device__ int   g_src[MAXE];
__device__ int   g_dst[MAXE];
__device__ int   g_cnt[MAXN];
__device__ int   g_scanA[MAXN];
__device__ int   g_blksum[256];
__device__ int   g_blkoff[256];
__device__ int   g_off[MAXN + 1];
__device__ int   g_cursor[MAXN];
__device__ int   g_is64;
// composed layer-1 weights (emb folded in)
__device__ float g_wlc[128 * 128];
__device__ float g_wrc[128 * 128];
__device__ float g_blc[128];
__device__ float g_brc[128];

// ---------------- small helpers ----------------
__device__ __forceinline__ float lk(float x) { return x > 0.0f ? x : NEG * x; }

__device__ __forceinline__ ull pk2(float x, float y) {
    ull r;
    asm("mov.b64 %0, {%1, %2};" : "=l"(r) : "f"(x), "f"(y));
    return r;
}
__device__ __forceinline__ void fma2(ull& d, ull a, ull b) {
    asm("fma.rn.f32x2 %0, %1, %2, %0;" : "+l"(d) : "l"(a), "l"(b));
}
__device__ __forceinline__ float2 up2(ull v) {
    float2 r;
    asm("mov.b64 {%0, %1}, %2;" : "=f"(r.x), "=f"(r.y) : "l"(v));
    return r;
}
__device__ __forceinline__ unsigned int tf32b(float x) {
    unsigned int r;
    asm("cvt.rna.tf32.f32 %0, %1;" : "=r"(r) : "f"(x));
    return r;
}
__device__ __forceinline__ void mma_tf32(float* d, const unsigned int* a,
                                         unsigned int b0, unsigned int b1) {
    asm("mma.sync.aligned.m16n8k8.row.col.f32.tf32.tf32.f32 "
        "{%0,%1,%2,%3}, {%4,%5,%6,%7}, {%8,%9}, {%0,%1,%2,%3};"
        : "+f"(d[0]), "+f"(d[1]), "+f"(d[2]), "+f"(d[3])
        : "r"(a[0]), "r"(a[1]), "r"(a[2]), "r"(a[3]), "r"(b0), "r"(b1));
}
__device__ __forceinline__ float4 cvt4(float4 v) {
    float4 t;
    t.x = __uint_as_float(tf32b(v.x));
    t.y = __uint_as_float(tf32b(v.y));
    t.z = __uint_as_float(tf32b(v.z));
    t.w = __uint_as_float(tf32b(v.w));
    return t;
}

// ---------------- merged dtype detection + count zeroing ----------------
__global__ void k_detzero(const void* __restrict__ idx, int E, int N) {
    int i = blockIdx.x * blockDim.x + threadIdx.x;
    if (i < N) g_cnt[i] = 0;
    if (i == 0) {
        const long long* p = (const long long*)idx;
        int ok = 1;
        int cnt = 64;
        if (2 * E < 64) cnt = 2 * E;
        for (int q = 0; q < cnt; q++) {
            long long v = p[q];
            if (v < 0 || v >= (long long)N) { ok = 0; break; }
        }
        g_is64 = ok;
    }
}

__global__ void k_prep(const void* __restrict__ idx, int E) {
    int e = blockIdx.x * blockDim.x + threadIdx.x;
    if (e >= E) return;
    int s, d;
    if (g_is64) {
        s = (int)((const long long*)idx)[e];
        d = (int)((const long long*)idx)[E + e];
    } else {
        s = ((const int*)idx)[e];
        d = ((const int*)idx)[E + e];
    }
    g_src[e] = s;
    g_dst[e] = d;
    atomicAdd(&g_cnt[d], 1);
}

// ---------------- CSR build: scan -> scatter ----------------
__global__ void k_scan_local(int N) {
    __shared__ int s[256];
    int b = blockIdx.x, t = threadIdx.x, i = b * 256 + t;
    int v = (i < N) ? g_cnt[i] + 1 : 0;
    s[t] = v;
    __syncthreads();
    for (int o = 1; o < 256; o <<= 1) {
        int x = (t >= o) ? s[t - o] : 0;
        __syncthreads();
        s[t] += x;
        __syncthreads();
    }
    if (i < N) g_scanA[i] = s[t];
    if (t == 255) g_blksum[b] = s[255];
}
__global__ void k_scan_blk(int nblk) {
    __shared__ int s[256];
    int t = threadIdx.x;
    int v = (t < nblk) ? g_blksum[t] : 0;
    s[t] = v;
    __syncthreads();
    for (int o = 1; o < 256; o <<= 1) {
        int x = (t >= o) ? s[t - o] : 0;
        __syncthreads();
        s[t] += x;
        __syncthreads();
    }
    g_blkoff[t] = s[t] - v;   // exclusive
}
__global__ void k_scan_add(int N, int T) {
    int i = blockIdx.x * blockDim.x + threadIdx.x;
    if (i < N) {
        int v = g_cnt[i] + 1;
        int off = g_scanA[i] - v + g_blkoff[i >> 8];
        g_off[i] = off;
        g_cursor[i] = off;
    }
    if (i == 0) g_off[N] = T;
}
// single packed int4 store per CSR slot
__global__ void k_scatter(int E, int T) {
    int e = blockIdx.x * blockDim.x + threadIdx.x;
    if (e >= T) return;
    int d, s;
    if (e < E) { d = g_dst[e]; s = g_src[e]; }
    else       { d = e - E;    s = d; }
    int pos = atomicAdd(&g_cursor[d], 1);
    g_pack[pos] = make_int4(e, s, d, 0);
}

// ---------------- self-loop attr from CSR (atomic-free) ----------------
__global__ void __launch_bounds__(256) k_loopcsr(const float* __restrict__ ea,
                                                 int E, int N) {
    int w = (blockIdx.x * blockDim.x + threadIdx.x) >> 5;
    int lane = threadIdx.x & 31;
    if (w >= N) return;
    int lo = g_off[w], hi = g_off[w + 1];
    float sum = 0.f;
    int cnt = 0;
    for (int p = lo; p < hi; p++) {
        int eid = g_pack[p].x;
        if (eid < E) { sum += ea[(size_t)eid * 32 + lane]; cnt++; }
    }
    g_loop[(size_t)w * 32 + lane] = sum / fmaxf((float)cnt, 1.f);
}

// ---------------- tf32 tensor-core GEMM (used for weight composition) --------
__global__ void __launch_bounds__(256) k_gemm_tc(const float* __restrict__ A,
                                                 const float* __restrict__ W,
                                                 const float* __restrict__ bias,
                                                 float* __restrict__ C, int M) {
    __shared__ float As[128][36];
    __shared__ float Ws[32][136];
    int tid  = threadIdx.x;
    int warp = tid >> 5, lane = tid & 31;
    int gid = lane >> 2, tig = lane & 3;
    int wr = warp & 3, wc = warp >> 2;
    int row0 = blockIdx.x * 128;

    float acc[2][8][4];
#pragma unroll
    for (int ar = 0; ar < 2; ar++)
#pragma unroll
        for (int ac = 0; ac < 8; ac++)
#pragma unroll
            for (int q = 0; q < 4; q++) acc[ar][ac][q] = 0.f;

    for (int kc = 0; kc < 128; kc += 32) {
        {
            int r  = tid >> 1;
            int k4 = (tid & 1) * 16;
            bool ok = (row0 + r) < M;
            const float* ap = A + (size_t)(row0 + r) * 128 + kc + k4;
#pragma unroll
            for (int q = 0; q < 4; q++) {
                float4 v = ok ? *(const float4*)(ap + q * 4)
                              : make_float4(0.f, 0.f, 0.f, 0.f);
                *(float4*)(&As[r][k4 + q * 4]) = cvt4(v);
            }
        }
        {
            int r  = tid >> 3;
            int c4 = (tid & 7) * 16;
            const float* wp = W + (size_t)(kc + r) * 128 + c4;
#pragma unroll
            for (int q = 0; q < 4; q++) {
                float4 v = *(const float4*)(wp + q * 4);
                *(float4*)(&Ws[r][c4 + q * 4]) = cvt4(v);
            }
        }
        __syncthreads();

#pragma unroll
        for (int ks = 0; ks < 4; ks++) {
            int k0 = ks * 8;
            unsigned int af[2][4];
#pragma unroll
            for (int ar = 0; ar < 2; ar++) {
                int rb = wr * 32 + ar * 16;
                af[ar][0] = __float_as_uint(As[rb + gid    ][k0 + tig]);
                af[ar][1] = __float_as_uint(As[rb + gid + 8][k0 + tig]);
                af[ar][2] = __float_as_uint(As[rb + gid    ][k0 + tig + 4]);
                af[ar][3] = __float_as_uint(As[rb + gid + 8][k0 + tig + 4]);
            }
#pragma unroll
            for (int ac = 0; ac < 8; ac++) {
                int cb = wc * 64 + ac * 8;
                unsigned int b0 = __float_as_uint(Ws[k0 + tig    ][cb + gid]);
                unsigned int b1 = __float_as_uint(Ws[k0 + tig + 4][cb + gid]);
                mma_tf32(acc[0][ac], af[0], b0, b1);
                mma_tf32(acc[1][ac], af[1], b0, b1);
            }
        }
        __syncthreads();
    }

#pragma unroll
    for (int ar = 0; ar < 2; ar++) {
        int rb = row0 + wr * 32 + ar * 16;
#pragma unroll
        for (int ac = 0; ac < 8; ac++) {
            int col = wc * 64 + ac * 8 + 2 * tig;
            float b0v = bias ? bias[col]     : 0.f;
            float b1v = bias ? bias[col + 1] : 0.f;
            int r0 = rb + gid, r1 = rb + gid + 8;
            if (r0 < M) {
                float2 v = make_float2(acc[ar][ac][0] + b0v, acc[ar][ac][1] + b1v);
                *(float2*)(C + (size_t)r0 * 128 + col) = v;
            }
            if (r1 < M) {
                float2 v = make_float2(acc[ar][ac][2] + b0v, acc[ar][ac][3] + b1v);
                *(float2*)(C + (size_t)r1 * 128 + col) = v;
            }
        }
    }
}

// ---------------- bias composition: blc = b_emb@Wl1 + bl1, brc = b_emb@Wr1 ----
__global__ void k_biascomp(const float* __restrict__ b_emb,
                           const float* __restrict__ Wl1,
                           const float* __restrict__ bl1,
                           const float* __restrict__ Wr1) {
    int c = threadIdx.x;   // 0..127
    const float* W = (blockIdx.x == 0) ? Wl1 : Wr1;
    float s = (blockIdx.x == 0) ? bl1[c] : 0.f;
    for (int k = 0; k < 128; k++) s += b_emb[k] * W[k * 128 + c];
    if (blockIdx.x == 0) g_blc[c] = s;
    else                 g_brc[c] = s;
}

// ---------------- fused xl/xr GEMM, software-pipelined K-chunks --------------
#define LR_SMF 13312

__global__ void __launch_bounds__(512) k_gemm_lr(const float* __restrict__ A,
                                                 const float* __restrict__ Wlp,
                                                 const float* __restrict__ blp,
                                                 const float* __restrict__ Wrp,
                                                 const float* __restrict__ brp,
                                                 float* __restrict__ Cl,
                                                 float* __restrict__ Cr, int M) {
    extern __shared__ float smlr[];
    float* As  = smlr;           // [128][36]
    float* Wsl = smlr + 4608;    // [32][136]
    float* Wsr = smlr + 8960;    // [32][136]
    int tid  = threadIdx.x;
    int warp = tid >> 5, lane = tid & 31;
    int gid = lane >> 2, tig = lane & 3;
    int wr = warp & 3, wc = warp >> 2;       // wc 0..3
    int row0 = blockIdx.x * 128;
    const float* Wsrc = (wc < 2) ? Wsl : Wsr;
    int cbase = (wc & 1) * 64;

    int rA  = tid >> 2, k4A = (tid & 3) * 8;
    int rW  = tid >> 4, c8W = (tid & 15) * 8;
    bool okA = (row0 + rA) < M;
    const float* apB = A   + (size_t)(row0 + rA) * 128 + k4A;
    const float* wlB = Wlp + (size_t)rW * 128 + c8W;
    const float* wrB = Wrp + (size_t)rW * 128 + c8W;

    float acc[2][8][4];
#pragma unroll
    for (int ar = 0; ar < 2; ar++)
#pragma unroll
        for (int ac = 0; ac < 8; ac++)
#pragma unroll
            for (int q = 0; q < 4; q++) acc[ar][ac][q] = 0.f;

    float4 pa0, pa1, pl0, pl1, pr0, pr1;
    pa0 = okA ? *(const float4*)(apB)     : make_float4(0.f, 0.f, 0.f, 0.f);
    pa1 = okA ? *(const float4*)(apB + 4) : make_float4(0.f, 0.f, 0.f, 0.f);
    pl0 = *(const float4*)(wlB);
    pl1 = *(const float4*)(wlB + 4);
    pr0 = *(const float4*)(wrB);
    pr1 = *(const float4*)(wrB + 4);

#pragma unroll
    for (int kc4 = 0; kc4 < 4; kc4++) {
        *(float4*)(&As[rA * 36 + k4A])       = cvt4(pa0);
        *(float4*)(&As[rA * 36 + k4A + 4])   = cvt4(pa1);
        *(float4*)(&Wsl[rW * 136 + c8W])     = cvt4(pl0);
        *(float4*)(&Wsl[rW * 136 + c8W + 4]) = cvt4(pl1);
        *(float4*)(&Wsr[rW * 136 + c8W])     = cvt4(pr0);
        *(float4*)(&Wsr[rW * 136 + c8W + 4]) = cvt4(pr1);
        __syncthreads();

        if (kc4 < 3) {
            int kc = (kc4 + 1) * 32;
            pa0 = okA ? *(const float4*)(apB + kc)     : make_float4(0.f, 0.f, 0.f, 0.f);
            pa1 = okA ? *(const float4*)(apB + kc + 4) : make_float4(0.f, 0.f, 0.f, 0.f);
            pl0 = *(const float4*)(wlB + (size_t)kc * 128);
            pl1 = *(const float4*)(wlB + (size_t)kc * 128 + 4);
            pr0 = *(const float4*)(wrB + (size_t)kc * 128);
            pr1 = *(const float4*)(wrB + (size_t)kc * 128 + 4);
        }

#pragma unroll
        for (int ks = 0; ks < 4; ks++) {
            int k0 = ks * 8;
            unsigned int af[2][4];
#pragma unroll
            for (int ar = 0; ar < 2; ar++) {
                int rb = wr * 32 + ar * 16;
                af[ar][0] = __float_as_uint(As[(rb + gid    ) * 36 + k0 + tig]);
                af[ar][1] = __float_as_uint(As[(rb + gid + 8) * 36 + k0 + tig]);
                af[ar][2] = __float_as_uint(As[(rb + gid    ) * 36 + k0 + tig + 4]);
                af[ar][3] = __float_as_uint(As[(rb + gid + 8) * 36 + k0 + tig + 4]);
            }
#pragma unroll
            for (int ac = 0; ac < 8; ac++) {
                int cb = cbase + ac * 8;
                unsigned int b0 = __float_as_uint(Wsrc[(k0 + tig    ) * 136 + cb + gid]);
                unsigned int b1 = __float_as_uint(Wsrc[(k0 + tig + 4) * 136 + cb + gid]);
                mma_tf32(acc[0][ac], af[0], b0, b1);
                mma_tf32(acc[1][ac], af[1], b0, b1);
            }
        }
        __syncthreads();
    }

    float* Cdst = (wc < 2) ? Cl : Cr;
    const float* bp = (wc < 2) ? blp : brp;
#pragma unroll
    for (int ar = 0; ar < 2; ar++) {
        int rb = row0 + wr * 32 + ar * 16;
#pragma unroll
        for (int ac = 0; ac < 8; ac++) {
            int col = cbase + ac * 8 + 2 * tig;
            float b0v = bp ? bp[col]     : 0.f;
            float b1v = bp ? bp[col + 1] : 0.f;
            int r0 = rb + gid, r1 = rb + gid + 8;
            if (r0 < M) {
                float2 v = make_float2(acc[ar][ac][0] + b0v, acc[ar][ac][1] + b1v);
                *(float2*)(Cdst + (size_t)r0 * 128 + col) = v;
            }
            if (r1 < M) {
                float2 v = make_float2(acc[ar][ac][2] + b0v, acc[ar][ac][3] + b1v);
                *(float2*)(Cdst + (size_t)r1 * 128 + col) = v;
            }
        }
    }
}

// ---------------- phase A: edge GEMM + score in CSR order ---------------------
// Dynamic smem layout (bytes):
//   As2 (ull[32][128], packed (v,v)) @0      -> 32768
//   Ws  (float[32][128])            @32768   -> 16384
//   ssrc @49152 (512), sdst @49664 (512)     total 50176
#define ESC_SMB 50176

__global__ void __launch_bounds__(256, 2) k_escore(const float* __restrict__ ea,
                                                   const float* __restrict__ We,
                                                   const float* __restrict__ att,
                                                   int E, int T) {
    extern __shared__ unsigned char esm[];
    ull*   As2  = (ull*)esm;                    // [k][row] packed pairs
    float* Ws   = (float*)(esm + 32768);        // [k*128 + col]
    int*   ssrc = (int*)(esm + 49152);
    int*   sdst = (int*)(esm + 49664);

    int tid = threadIdx.x;
    int e0  = blockIdx.x * 128;
    int ty = tid >> 4, tx = tid & 15;

    {
        const float4* src = (const float4*)We;
        float4* dstp = (float4*)Ws;
#pragma unroll
        for (int q = 0; q < 4; q++) dstp[tid + q * 256] = src[tid + q * 256];
    }
    int eid_r = 0;   // eid for the A-fill row this thread handles
    if (tid < 128) {
        int p_ = e0 + tid;
        if (p_ < T) {
            int4 pk = g_pack[p_];
            ssrc[tid] = pk.y;
            sdst[tid] = pk.z;
        } else {
            ssrc[tid] = sdst[tid] = 0;
        }
    }
    {
        int arow = tid >> 1;
        int kb   = (tid & 1) * 16;
        int p_   = e0 + arow;
        const float* rowp = (const float*)0;
        if (p_ < T) {
            eid_r = g_pack[p_].x;
            rowp = (eid_r < E) ? (ea + (size_t)eid_r * 32)
                               : (g_loop + (size_t)(eid_r - E) * 32);
        }
#pragma unroll
        for (int q = 0; q < 4; q++) {
            float4 v = rowp ? *(const float4*)(rowp + kb + q * 4)
                            : make_float4(0.f, 0.f, 0.f, 0.f);
            As2[(size_t)(kb + q * 4 + 0) * 128 + arow] = pk2(v.x, v.x);
            As2[(size_t)(kb + q * 4 + 1) * 128 + arow] = pk2(v.y, v.y);
            As2[(size_t)(kb + q * 4 + 2) * 128 + arow] = pk2(v.z, v.z);
            As2[(size_t)(kb + q * 4 + 3) * 128 + arow] = pk2(v.w, v.w);
        }
    }
    __syncthreads();

    ull acc2[8][4];
#pragma unroll
    for (int i = 0; i < 8; i++)
#pragma unroll
        for (int j = 0; j < 4; j++) acc2[i][j] = 0ULL;

#pragma unroll
    for (int k = 0; k < 32; k++) {
        ull a2[8];
        ull b2[4];
        const ull* arp = As2 + (size_t)k * 128 + ty * 8;
#pragma unroll
        for (int i = 0; i < 8; i++) a2[i] = arp[i];
        const ull* wp = (const ull*)(Ws + (size_t)k * 128 + tx * 8);
        b2[0] = wp[0]; b2[1] = wp[1]; b2[2] = wp[2]; b2[3] = wp[3];
#pragma unroll
        for (int i = 0; i < 8; i++)
#pragma unroll
            for (int j = 0; j < 4; j++) fma2(acc2[i][j], a2[i], b2[j]);
    }

    // epilogue: logit partial per (row, tx), half-warp shfl reduce, lane-0 store
    float4 at0 = *(const float4*)(att + tx * 8);
    float4 at1 = *(const float4*)(att + tx * 8 + 4);
#pragma unroll
    for (int i = 0; i < 8; i++) {
        int r = ty * 8 + i;
        int s = ssrc[r], d = sdst[r];
        const float* xlp = g_xl + (size_t)s * HID + tx * 8;
        const float* xrp = g_xr + (size_t)d * HID + tx * 8;
        float4 xl0 = *(const float4*)(xlp);
        float4 xl1 = *(const float4*)(xlp + 4);
        float4 xr0 = *(const float4*)(xrp);
        float4 xr1 = *(const float4*)(xrp + 4);
        float2 v0 = up2(acc2[i][0]);
        float2 v1 = up2(acc2[i][1]);
        float2 v2 = up2(acc2[i][2]);
        float2 v3 = up2(acc2[i][3]);
        float p = lk(xl0.x + xr0.x + v0.x) * at0.x
                + lk(xl0.y + xr0.y + v0.y) * at0.y
                + lk(xl0.z + xr0.z + v1.x) * at0.z
                + lk(xl0.w + xr0.w + v1.y) * at0.w
                + lk(xl1.x + xr1.x + v2.x) * at1.x
                + lk(xl1.y + xr1.y + v2.y) * at1.y
                + lk(xl1.z + xr1.z + v3.x) * at1.z
                + lk(xl1.w + xr1.w + v3.y) * at1.w;
        // reduce 16 partials within the half-warp (lanes sharing ty)
        p += __shfl_xor_sync(0xFFFFFFFFu, p, 1, 32);
        p += __shfl_xor_sync(0xFFFFFFFFu, p, 2, 32);
        p += __shfl_xor_sync(0xFFFFFFFFu, p, 4, 32);
        p += __shfl_xor_sync(0xFFFFFFFFu, p, 8, 32);
        if (tx == 0) {
            int p_ = e0 + r;
            if (p_ < T) g_ez[p_] = __expf(p);
        }
    }
}

// ---------------- phase B: CSR aggregation + norm + bias + silu ----------------
__global__ void __launch_bounds__(256) k_aggr(const float* __restrict__ bo,
                                              float* __restrict__ out,
                                              int E, int N) {
    int w = (blockIdx.x * blockDim.x + threadIdx.x) >> 5;
    int lane = threadIdx.x & 31;
    if (w >= N) return;
    int lo = g_off[w], hi = g_off[w + 1];
    int c = lane * 4;
    float ax = 0.f, ay = 0.f, az = 0.f, aw = 0.f, den = 0.f;
    for (int p = lo; p < hi; p++) {
        float ez = g_ez[p];
        int s = g_pack[p].y;
        float4 xl = *(const float4*)(g_xl + (size_t)s * HID + c);
        ax += ez * xl.x; ay += ez * xl.y; az += ez * xl.z; aw += ez * xl.w;
        den += ez;
    }
    float inv = 1.0f / den;
    float4 b = *(const float4*)(bo + c);
    float vx = ax * inv + b.x;
    float vy = ay * inv + b.y;
    float vz = az * inv + b.z;
    float vw = aw * inv + b.w;
    float4 o;
    o.x = vx / (1.0f + __expf(-vx));
    o.y = vy / (1.0f + __expf(-vy));
    o.z = vz / (1.0f + __expf(-vz));
    o.w = vw / (1.0f + __expf(-vw));
    *(float4*)(out + (size_t)w * HID + c) = o;
}

// ---------------- host orchestration ----------------
extern "C" void kernel_launch(void* const* d_in, const int* in_sizes, int n_in,
                              void* d_out, int out_size) {
    const float* x    = (const float*)d_in[0];
    const void*  eidx = d_in[1];
    const float* ea   = (const float*)d_in[2];
    const float* W_emb = (const float*)d_in[3];
    const float* b_emb = (const float*)d_in[4];
    const float* Wl[2]  = {(const float*)d_in[5],  (const float*)d_in[11]};
    const float* bl[2]  = {(const float*)d_in[6],  (const float*)d_in[12]};
    const float* Wr[2]  = {(const float*)d_in[7],  (const float*)d_in[13]};
    const float* We[2]  = {(const float*)d_in[8],  (const float*)d_in[14]};
    const float* att[2] = {(const float*)d_in[9],  (const float*)d_in[15]};
    const float* bo[2]  = {(const float*)d_in[10], (const float*)d_in[16]};

    int N = in_sizes[0] / HID;
    int E = in_sizes[2] / 32;
    int T = E + N;

    float *p_h, *p_xl, *p_xr, *p_wlc, *p_wrc, *p_blc, *p_brc;
    cudaGetSymbolAddress((void**)&p_h,   g_h);
    cudaGetSymbolAddress((void**)&p_xl,  g_xl);
    cudaGetSymbolAddress((void**)&p_xr,  g_xr);
    cudaGetSymbolAddress((void**)&p_wlc, g_wlc);
    cudaGetSymbolAddress((void**)&p_wrc, g_wrc);
    cudaGetSymbolAddress((void**)&p_blc, g_blc);
    cudaGetSymbolAddress((void**)&p_brc, g_brc);

    int gb_n = (N + 127) / 128;
    int nblk = (N + 255) / 256;
    int wb_n = (N * 32 + 255) / 256;

    int lr_smem = LR_SMF * 4;   // 53 KB
    cudaFuncSetAttribute(k_gemm_lr, cudaFuncAttributeMaxDynamicSharedMemorySize, lr_smem);
    cudaFuncSetAttribute(k_escore, cudaFuncAttributeMaxDynamicSharedMemorySize, ESC_SMB);

    // one-time resources (created on the first, non-captured correctness call)
    static cudaStream_t s2 = nullptr;
    static cudaEvent_t  evFork = nullptr, evJoin = nullptr;
    if (s2 == nullptr) {
        cudaStreamCreate(&s2);
        cudaEventCreateWithFlags(&evFork, cudaEventDisableTiming);
        cudaEventCreateWithFlags(&evJoin, cudaEventDisableTiming);
    }

    // ---- fork: CSR build chain on s2, GEMM front-end on the main stream ----
    cudaEventRecord(evFork, 0);
    cudaStreamWaitEvent(s2, evFork, 0);

    // chain B (s2): CSR build + self-loop attrs
    k_detzero<<<nblk, 256, 0, s2>>>(eidx, E, N);
    k_prep<<<(E + 255) / 256, 256, 0, s2>>>(eidx, E);
    k_scan_local<<<nblk, 256, 0, s2>>>(N);
    k_scan_blk<<<1, 256, 0, s2>>>(nblk);
    k_scan_add<<<nblk, 256, 0, s2>>>(N, T);
    k_scatter<<<(T + 255) / 256, 256, 0, s2>>>(E, T);
    k_loopcsr<<<wb_n, 256, 0, s2>>>(ea, E, N);
    cudaEventRecord(evJoin, s2);

    // chain A (main): weight composition + layer-1 node transforms
    k_gemm_tc<<<1, 256>>>(W_emb, Wl[0], nullptr, p_wlc, 128);
    k_gemm_tc<<<1, 256>>>(W_emb, Wr[0], nullptr, p_wrc, 128);
    k_biascomp<<<2, 128>>>(b_emb, Wl[0], bl[0], Wr[0]);
    k_gemm_lr<<<gb_n, 512, lr_smem>>>(x, p_wlc, p_blc, p_wrc, p_brc,
                                      p_xl, p_xr, N);

    // ---- join ----
    cudaStreamWaitEvent(0, evJoin, 0);

    int eb = (T + 127) / 128;
    // layer 1
    k_escore<<<eb, 256, ESC_SMB>>>(ea, We[0], att[0], E, T);
    k_aggr<<<wb_n, 256>>>(bo[0], p_h, E, N);
    // layer 2
    k_gemm_lr<<<gb_n, 512, lr_smem>>>(p_h, Wl[1], bl[1], Wr[1], nullptr,
                                      p_xl, p_xr, N);
    k_escore<<<eb, 256, ESC_SMB>>>(ea, We[1], att[1], E, T);
    k_aggr<<<wb_n, 256>>>(bo[1], (float*)d_out, E, N);
}

// round 17
// speedup vs baseline: 1.1169x; 1.1169x over previous
#include <cuda_runtime.h>
#include <math.h>

#define HID 128
#define NEG 0.2f
#define MAXN 50000
#define MAXE 800000
#define MAXT (MAXE + MAXN)

typedef unsigned long long ull;

// ---------------- static scratch (no allocations allowed) ----------------
__device__ float g_h  [MAXN * HID];
__device__ float g_xl [MAXN * HID];
__device__ float g_xr [MAXN * HID];
__device__ float g_loop[MAXN * 32];
__device__ float g_ez  [MAXT];     // indexed by CSR position
__device__ int4  g_pack[MAXT];     // {eid, src, dst, 0} per CSR position
__device__ int   g_src[MAXE];
__device__ int   g_dst[MAXE];
__device__ int   g_cnt[MAXN];
__device__ int   g_scanA[MAXN];
__device__ int   g_blksum[256];
__device__ int   g_blkoff[256];
__device__ int   g_off[MAXN + 1];
__device__ int   g_cursor[MAXN];
__device__ int   g_is64;
// composed layer-1 weights (emb folded in)
__device__ float g_wlc[128 * 128];
__device__ float g_wrc[128 * 128];
__device__ float g_blc[128];
__device__ float g_brc[128];

// ---------------- small helpers ----------------
__device__ __forceinline__ float lk(float x) { return x > 0.0f ? x : NEG * x; }

__device__ __forceinline__ ull pk2(float x, float y) {
    ull r;
    asm("mov.b64 %0, {%1, %2};" : "=l"(r) : "f"(x), "f"(y));
    return r;
}
__device__ __forceinline__ void fma2(ull& d, ull a, ull b) {
    asm("fma.rn.f32x2 %0, %1, %2, %0;" : "+l"(d) : "l"(a), "l"(b));
}
__device__ __forceinline__ float2 up2(ull v) {
    float2 r;
    asm("mov.b64 {%0, %1}, %2;" : "=f"(r.x), "=f"(r.y) : "l"(v));
    return r;
}
__device__ __forceinline__ unsigned int tf32b(float x) {
    unsigned int r;
    asm("cvt.rna.tf32.f32 %0, %1;" : "=r"(r) : "f"(x));
    return r;
}
__device__ __forceinline__ void mma_tf32(float* d, const unsigned int* a,
                                         unsigned int b0, unsigned int b1) {
    asm("mma.sync.aligned.m16n8k8.row.col.f32.tf32.tf32.f32 "
        "{%0,%1,%2,%3}, {%4,%5,%6,%7}, {%8,%9}, {%0,%1,%2,%3};"
        : "+f"(d[0]), "+f"(d[1]), "+f"(d[2]), "+f"(d[3])
        : "r"(a[0]), "r"(a[1]), "r"(a[2]), "r"(a[3]), "r"(b0), "r"(b1));
}
__device__ __forceinline__ float4 cvt4(float4 v) {
    float4 t;
    t.x = __uint_as_float(tf32b(v.x));
    t.y = __uint_as_float(tf32b(v.y));
    t.z = __uint_as_float(tf32b(v.z));
    t.w = __uint_as_float(tf32b(v.w));
    return t;
}

// ---------------- merged dtype detection + count zeroing ----------------
__global__ void k_detzero(const void* __restrict__ idx, int E, int N) {
    int i = blockIdx.x * blockDim.x + threadIdx.x;
    if (i < N) g_cnt[i] = 0;
    if (i == 0) {
        const long long* p = (const long long*)idx;
        int ok = 1;
        int cnt = 64;
        if (2 * E < 64) cnt = 2 * E;
        for (int q = 0; q < cnt; q++) {
            long long v = p[q];
            if (v < 0 || v >= (long long)N) { ok = 0; break; }
        }
        g_is64 = ok;
    }
}

__global__ void k_prep(const void* __restrict__ idx, int E) {
    int e = blockIdx.x * blockDim.x + threadIdx.x;
    if (e >= E) return;
    int s, d;
    if (g_is64) {
        s = (int)((const long long*)idx)[e];
        d = (int)((const long long*)idx)[E + e];
    } else {
        s = ((const int*)idx)[e];
        d = ((const int*)idx)[E + e];
    }
    g_src[e] = s;
    g_dst[e] = d;
    atomicAdd(&g_cnt[d], 1);
}

// ---------------- CSR build: scan -> scatter ----------------
__global__ void k_scan_local(int N) {
    __shared__ int s[256];
    int b = blockIdx.x, t = threadIdx.x, i = b * 256 + t;
    int v = (i < N) ? g_cnt[i] + 1 : 0;
    s[t] = v;
    __syncthreads();
    for (int o = 1; o < 256; o <<= 1) {
        int x = (t >= o) ? s[t - o] : 0;
        __syncthreads();
        s[t] += x;
        __syncthreads();
    }
    if (i < N) g_scanA[i] = s[t];
    if (t == 255) g_blksum[b] = s[255];
}
__global__ void k_scan_blk(int nblk) {
    __shared__ int s[256];
    int t = threadIdx.x;
    int v = (t < nblk) ? g_blksum[t] : 0;
    s[t] = v;
    __syncthreads();
    for (int o = 1; o < 256; o <<= 1) {
        int x = (t >= o) ? s[t - o] : 0;
        __syncthreads();
        s[t] += x;
        __syncthreads();
    }
    g_blkoff[t] = s[t] - v;   // exclusive
}
__global__ void k_scan_add(int N, int T) {
    int i = blockIdx.x * blockDim.x + threadIdx.x;
    if (i < N) {
        int v = g_cnt[i] + 1;
        int off = g_scanA[i] - v + g_blkoff[i >> 8];
        g_off[i] = off;
        g_cursor[i] = off;
    }
    if (i == 0) g_off[N] = T;
}
// single packed int4 store per CSR slot
__global__ void k_scatter(int E, int T) {
    int e = blockIdx.x * blockDim.x + threadIdx.x;
    if (e >= T) return;
    int d, s;
    if (e < E) { d = g_dst[e]; s = g_src[e]; }
    else       { d = e - E;    s = d; }
    int pos = atomicAdd(&g_cursor[d], 1);
    g_pack[pos] = make_int4(e, s, d, 0);
}

// ---------------- self-loop attr from CSR (atomic-free) ----------------
__global__ void __launch_bounds__(256) k_loopcsr(const float* __restrict__ ea,
                                                 int E, int N) {
    int w = (blockIdx.x * blockDim.x + threadIdx.x) >> 5;
    int lane = threadIdx.x & 31;
    if (w >= N) return;
    int lo = g_off[w], hi = g_off[w + 1];
    float sum = 0.f;
    int cnt = 0;
    for (int p = lo; p < hi; p++) {
        int eid = g_pack[p].x;
        if (eid < E) { sum += ea[(size_t)eid * 32 + lane]; cnt++; }
    }
    g_loop[(size_t)w * 32 + lane] = sum / fmaxf((float)cnt, 1.f);
}

// ---------------- tf32 tensor-core GEMM (used for weight composition) --------
__global__ void __launch_bounds__(256) k_gemm_tc(const float* __restrict__ A,
                                                 const float* __restrict__ W,
                                                 const float* __restrict__ bias,
                                                 float* __restrict__ C, int M) {
    __shared__ float As[128][36];
    __shared__ float Ws[32][136];
    int tid  = threadIdx.x;
    int warp = tid >> 5, lane = tid & 31;
    int gid = lane >> 2, tig = lane & 3;
    int wr = warp & 3, wc = warp >> 2;
    int row0 = blockIdx.x * 128;

    float acc[2][8][4];
#pragma unroll
    for (int ar = 0; ar < 2; ar++)
#pragma unroll
        for (int ac = 0; ac < 8; ac++)
#pragma unroll
            for (int q = 0; q < 4; q++) acc[ar][ac][q] = 0.f;

    for (int kc = 0; kc < 128; kc += 32) {
        {
            int r  = tid >> 1;
            int k4 = (tid & 1) * 16;
            bool ok = (row0 + r) < M;
            const float* ap = A + (size_t)(row0 + r) * 128 + kc + k4;
#pragma unroll
            for (int q = 0; q < 4; q++) {
                float4 v = ok ? *(const float4*)(ap + q * 4)
                              : make_float4(0.f, 0.f, 0.f, 0.f);
                *(float4*)(&As[r][k4 + q * 4]) = cvt4(v);
            }
        }
        {
            int r  = tid >> 3;
            int c4 = (tid & 7) * 16;
            const float* wp = W + (size_t)(kc + r) * 128 + c4;
#pragma unroll
            for (int q = 0; q < 4; q++) {
                float4 v = *(const float4*)(wp + q * 4);
                *(float4*)(&Ws[r][c4 + q * 4]) = cvt4(v);
            }
        }
        __syncthreads();

#pragma unroll
        for (int ks = 0; ks < 4; ks++) {
            int k0 = ks * 8;
            unsigned int af[2][4];
#pragma unroll
            for (int ar = 0; ar < 2; ar++) {
                int rb = wr * 32 + ar * 16;
                af[ar][0] = __float_as_uint(As[rb + gid    ][k0 + tig]);
                af[ar][1] = __float_as_uint(As[rb + gid + 8][k0 + tig]);
                af[ar][2] = __float_as_uint(As[rb + gid    ][k0 + tig + 4]);
                af[ar][3] = __float_as_uint(As[rb + gid + 8][k0 + tig + 4]);
            }
#pragma unroll
            for (int ac = 0; ac < 8; ac++) {
                int cb = wc * 64 + ac * 8;
                unsigned int b0 = __float_as_uint(Ws[k0 + tig    ][cb + gid]);
                unsigned int b1 = __float_as_uint(Ws[k0 + tig + 4][cb + gid]);
                mma_tf32(acc[0][ac], af[0], b0, b1);
                mma_tf32(acc[1][ac], af[1], b0, b1);
            }
        }
        __syncthreads();
    }

#pragma unroll
    for (int ar = 0; ar < 2; ar++) {
        int rb = row0 + wr * 32 + ar * 16;
#pragma unroll
        for (int ac = 0; ac < 8; ac++) {
            int col = wc * 64 + ac * 8 + 2 * tig;
            float b0v = bias ? bias[col]     : 0.f;
            float b1v = bias ? bias[col + 1] : 0.f;
            int r0 = rb + gid, r1 = rb + gid + 8;
            if (r0 < M) {
                float2 v = make_float2(acc[ar][ac][0] + b0v, acc[ar][ac][1] + b1v);
                *(float2*)(C + (size_t)r0 * 128 + col) = v;
            }
            if (r1 < M) {
                float2 v = make_float2(acc[ar][ac][2] + b0v, acc[ar][ac][3] + b1v);
                *(float2*)(C + (size_t)r1 * 128 + col) = v;
            }
        }
    }
}

// ---------------- bias composition: blc = b_emb@Wl1 + bl1, brc = b_emb@Wr1 ----
__global__ void k_biascomp(const float* __restrict__ b_emb,
                           const float* __restrict__ Wl1,
                           const float* __restrict__ bl1,
                           const float* __restrict__ Wr1) {
    int c = threadIdx.x;   // 0..127
    const float* W = (blockIdx.x == 0) ? Wl1 : Wr1;
    float s = (blockIdx.x == 0) ? bl1[c] : 0.f;
    for (int k = 0; k < 128; k++) s += b_emb[k] * W[k * 128 + c];
    if (blockIdx.x == 0) g_blc[c] = s;
    else                 g_brc[c] = s;
}

// ---------------- fused xl/xr GEMM, software-pipelined K-chunks --------------
#define LR_SMF 13312

__global__ void __launch_bounds__(512) k_gemm_lr(const float* __restrict__ A,
                                                 const float* __restrict__ Wlp,
                                                 const float* __restrict__ blp,
                                                 const float* __restrict__ Wrp,
                                                 const float* __restrict__ brp,
                                                 float* __restrict__ Cl,
                                                 float* __restrict__ Cr, int M) {
    extern __shared__ float smlr[];
    float* As  = smlr;           // [128][36]
    float* Wsl = smlr + 4608;    // [32][136]
    float* Wsr = smlr + 8960;    // [32][136]
    int tid  = threadIdx.x;
    int warp = tid >> 5, lane = tid & 31;
    int gid = lane >> 2, tig = lane & 3;
    int wr = warp & 3, wc = warp >> 2;       // wc 0..3
    int row0 = blockIdx.x * 128;
    const float* Wsrc = (wc < 2) ? Wsl : Wsr;
    int cbase = (wc & 1) * 64;

    int rA  = tid >> 2, k4A = (tid & 3) * 8;
    int rW  = tid >> 4, c8W = (tid & 15) * 8;
    bool okA = (row0 + rA) < M;
    const float* apB = A   + (size_t)(row0 + rA) * 128 + k4A;
    const float* wlB = Wlp + (size_t)rW * 128 + c8W;
    const float* wrB = Wrp + (size_t)rW * 128 + c8W;

    float acc[2][8][4];
#pragma unroll
    for (int ar = 0; ar < 2; ar++)
#pragma unroll
        for (int ac = 0; ac < 8; ac++)
#pragma unroll
            for (int q = 0; q < 4; q++) acc[ar][ac][q] = 0.f;

    float4 pa0, pa1, pl0, pl1, pr0, pr1;
    pa0 = okA ? *(const float4*)(apB)     : make_float4(0.f, 0.f, 0.f, 0.f);
    pa1 = okA ? *(const float4*)(apB + 4) : make_float4(0.f, 0.f, 0.f, 0.f);
    pl0 = *(const float4*)(wlB);
    pl1 = *(const float4*)(wlB + 4);
    pr0 = *(const float4*)(wrB);
    pr1 = *(const float4*)(wrB + 4);

#pragma unroll
    for (int kc4 = 0; kc4 < 4; kc4++) {
        *(float4*)(&As[rA * 36 + k4A])       = cvt4(pa0);
        *(float4*)(&As[rA * 36 + k4A + 4])   = cvt4(pa1);
        *(float4*)(&Wsl[rW * 136 + c8W])     = cvt4(pl0);
        *(float4*)(&Wsl[rW * 136 + c8W + 4]) = cvt4(pl1);
        *(float4*)(&Wsr[rW * 136 + c8W])     = cvt4(pr0);
        *(float4*)(&Wsr[rW * 136 + c8W + 4]) = cvt4(pr1);
        __syncthreads();

        if (kc4 < 3) {
            int kc = (kc4 + 1) * 32;
            pa0 = okA ? *(const float4*)(apB + kc)     : make_float4(0.f, 0.f, 0.f, 0.f);
            pa1 = okA ? *(const float4*)(apB + kc + 4) : make_float4(0.f, 0.f, 0.f, 0.f);
            pl0 = *(const float4*)(wlB + (size_t)kc * 128);
            pl1 = *(const float4*)(wlB + (size_t)kc * 128 + 4);
            pr0 = *(const float4*)(wrB + (size_t)kc * 128);
            pr1 = *(const float4*)(wrB + (size_t)kc * 128 + 4);
        }

#pragma unroll
        for (int ks = 0; ks < 4; ks++) {
            int k0 = ks * 8;
            unsigned int af[2][4];
#pragma unroll
            for (int ar = 0; ar < 2; ar++) {
                int rb = wr * 32 + ar * 16;
                af[ar][0] = __float_as_uint(As[(rb + gid    ) * 36 + k0 + tig]);
                af[ar][1] = __float_as_uint(As[(rb + gid + 8) * 36 + k0 + tig]);
                af[ar][2] = __float_as_uint(As[(rb + gid    ) * 36 + k0 + tig + 4]);
                af[ar][3] = __float_as_uint(As[(rb + gid + 8) * 36 + k0 + tig + 4]);
            }
#pragma unroll
            for (int ac = 0; ac < 8; ac++) {
                int cb = cbase + ac * 8;
                unsigned int b0 = __float_as_uint(Wsrc[(k0 + tig    ) * 136 + cb + gid]);
                unsigned int b1 = __float_as_uint(Wsrc[(k0 + tig + 4) * 136 + cb + gid]);
                mma_tf32(acc[0][ac], af[0], b0, b1);
                mma_tf32(acc[1][ac], af[1], b0, b1);
            }
        }
        __syncthreads();
    }

    float* Cdst = (wc < 2) ? Cl : Cr;
    const float* bp = (wc < 2) ? blp : brp;
#pragma unroll
    for (int ar = 0; ar < 2; ar++) {
        int rb = row0 + wr * 32 + ar * 16;
#pragma unroll
        for (int ac = 0; ac < 8; ac++) {
            int col = cbase + ac * 8 + 2 * tig;
            float b0v = bp ? bp[col]     : 0.f;
            float b1v = bp ? bp[col + 1] : 0.f;
            int r0 = rb + gid, r1 = rb + gid + 8;
            if (r0 < M) {
                float2 v = make_float2(acc[ar][ac][0] + b0v, acc[ar][ac][1] + b1v);
                *(float2*)(Cdst + (size_t)r0 * 128 + col) = v;
            }
            if (r1 < M) {
                float2 v = make_float2(acc[ar][ac][2] + b0v, acc[ar][ac][3] + b1v);
                *(float2*)(Cdst + (size_t)r1 * 128 + col) = v;
            }
        }
    }
}

// ---------------- phase A: edge GEMM + score in CSR order ---------------------
// Dynamic smem layout (bytes):
//   As2 (ull[32][128], packed (v,v)) @0      -> 32768
//   Ws  (float[32][128])            @32768   -> 16384
//   ssrc @49152 (512), sdst @49664 (512)
//   sp (float[128][17]) @50176              -> 8704   total 58880
#define ESC_SMB 58880

__global__ void __launch_bounds__(256, 2) k_escore(const float* __restrict__ ea,
                                                   const float* __restrict__ We,
                                                   const float* __restrict__ att,
                                                   int E, int T) {
    extern __shared__ unsigned char esm[];
    ull*   As2  = (ull*)esm;                    // [k][row] packed pairs
    float* Ws   = (float*)(esm + 32768);        // [k*128 + col]
    int*   ssrc = (int*)(esm + 49152);
    int*   sdst = (int*)(esm + 49664);
    float* sp   = (float*)(esm + 50176);        // [row*17 + tx]

    int tid = threadIdx.x;
    int e0  = blockIdx.x * 128;
    int ty = tid >> 4, tx = tid & 15;

    {
        const float4* src = (const float4*)We;
        float4* dstp = (float4*)Ws;
#pragma unroll
        for (int q = 0; q < 4; q++) dstp[tid + q * 256] = src[tid + q * 256];
    }
    if (tid < 128) {
        int p_ = e0 + tid;
        if (p_ < T) {
            int4 pk = g_pack[p_];
            ssrc[tid] = pk.y;
            sdst[tid] = pk.z;
        } else {
            ssrc[tid] = sdst[tid] = 0;
        }
    }
    {
        int arow = tid >> 1;
        int kb   = (tid & 1) * 16;
        int p_   = e0 + arow;
        const float* rowp = (const float*)0;
        if (p_ < T) {
            int eid = g_pack[p_].x;
            rowp = (eid < E) ? (ea + (size_t)eid * 32)
                             : (g_loop + (size_t)(eid - E) * 32);
        }
#pragma unroll
        for (int q = 0; q < 4; q++) {
            float4 v = rowp ? *(const float4*)(rowp + kb + q * 4)
                            : make_float4(0.f, 0.f, 0.f, 0.f);
            As2[(size_t)(kb + q * 4 + 0) * 128 + arow] = pk2(v.x, v.x);
            As2[(size_t)(kb + q * 4 + 1) * 128 + arow] = pk2(v.y, v.y);
            As2[(size_t)(kb + q * 4 + 2) * 128 + arow] = pk2(v.z, v.z);
            As2[(size_t)(kb + q * 4 + 3) * 128 + arow] = pk2(v.w, v.w);
        }
    }
    __syncthreads();

    ull acc2[8][4];
#pragma unroll
    for (int i = 0; i < 8; i++)
#pragma unroll
        for (int j = 0; j < 4; j++) acc2[i][j] = 0ULL;

#pragma unroll
    for (int k = 0; k < 32; k++) {
        ull a2[8];
        ull b2[4];
        const ull* arp = As2 + (size_t)k * 128 + ty * 8;
#pragma unroll
        for (int i = 0; i < 8; i++) a2[i] = arp[i];
        const ull* wp = (const ull*)(Ws + (size_t)k * 128 + tx * 8);
        b2[0] = wp[0]; b2[1] = wp[1]; b2[2] = wp[2]; b2[3] = wp[3];
#pragma unroll
        for (int i = 0; i < 8; i++)
#pragma unroll
            for (int j = 0; j < 4; j++) fma2(acc2[i][j], a2[i], b2[j]);
    }

    float4 at0 = *(const float4*)(att + tx * 8);
    float4 at1 = *(const float4*)(att + tx * 8 + 4);
#pragma unroll
    for (int i = 0; i < 8; i++) {
        int r = ty * 8 + i;
        int s = ssrc[r], d = sdst[r];
        const float* xlp = g_xl + (size_t)s * HID + tx * 8;
        const float* xrp = g_xr + (size_t)d * HID + tx * 8;
        float4 xl0 = *(const float4*)(xlp);
        float4 xl1 = *(const float4*)(xlp + 4);
        float4 xr0 = *(const float4*)(xrp);
        float4 xr1 = *(const float4*)(xrp + 4);
        float2 v0 = up2(acc2[i][0]);
        float2 v1 = up2(acc2[i][1]);
        float2 v2 = up2(acc2[i][2]);
        float2 v3 = up2(acc2[i][3]);
        float p = lk(xl0.x + xr0.x + v0.x) * at0.x
                + lk(xl0.y + xr0.y + v0.y) * at0.y
                + lk(xl0.z + xr0.z + v1.x) * at0.z
                + lk(xl0.w + xr0.w + v1.y) * at0.w
                + lk(xl1.x + xr1.x + v2.x) * at1.x
                + lk(xl1.y + xr1.y + v2.y) * at1.y
                + lk(xl1.z + xr1.z + v3.x) * at1.z
                + lk(xl1.w + xr1.w + v3.y) * at1.w;
        sp[r * 17 + tx] = p;
    }
    __syncthreads();

    if (tid < 128) {
        float sum = 0.f;
#pragma unroll
        for (int j = 0; j < 16; j++) sum += sp[tid * 17 + j];
        int p_ = e0 + tid;
        if (p_ < T) g_ez[p_] = __expf(sum);
    }
}

// ---------------- phase B: CSR aggregation + norm + bias + silu ----------------
__global__ void __launch_bounds__(256) k_aggr(const float* __restrict__ bo,
                                              float* __restrict__ out,
                                              int E, int N) {
    int w = (blockIdx.x * blockDim.x + threadIdx.x) >> 5;
    int lane = threadIdx.x & 31;
    if (w >= N) return;
    int lo = g_off[w], hi = g_off[w + 1];
    int c = lane * 4;
    float ax = 0.f, ay = 0.f, az = 0.f, aw = 0.f, den = 0.f;
    for (int p = lo; p < hi; p++) {
        float ez = g_ez[p];
        int s = g_pack[p].y;
        float4 xl = *(const float4*)(g_xl + (size_t)s * HID + c);
        ax += ez * xl.x; ay += ez * xl.y; az += ez * xl.z; aw += ez * xl.w;
        den += ez;
    }
    float inv = 1.0f / den;
    float4 b = *(const float4*)(bo + c);
    float vx = ax * inv + b.x;
    float vy = ay * inv + b.y;
    float vz = az * inv + b.z;
    float vw = aw * inv + b.w;
    float4 o;
    o.x = vx / (1.0f + __expf(-vx));
    o.y = vy / (1.0f + __expf(-vy));
    o.z = vz / (1.0f + __expf(-vz));
    o.w = vw / (1.0f + __expf(-vw));
    *(float4*)(out + (size_t)w * HID + c) = o;
}

// ---------------- host orchestration ----------------
extern "C" void kernel_launch(void* const* d_in, const int* in_sizes, int n_in,
                              void* d_out, int out_size) {
    const float* x    = (const float*)d_in[0];
    const void*  eidx = d_in[1];
    const float* ea   = (const float*)d_in[2];
    const float* W_emb = (const float*)d_in[3];
    const float* b_emb = (const float*)d_in[4];
    const float* Wl[2]  = {(const float*)d_in[5],  (const float*)d_in[11]};
    const float* bl[2]  = {(const float*)d_in[6],  (const float*)d_in[12]};
    const float* Wr[2]  = {(const float*)d_in[7],  (const float*)d_in[13]};
    const float* We[2]  = {(const float*)d_in[8],  (const float*)d_in[14]};
    const float* att[2] = {(const float*)d_in[9],  (const float*)d_in[15]};
    const float* bo[2]  = {(const float*)d_in[10], (const float*)d_in[16]};

    int N = in_sizes[0] / HID;
    int E = in_sizes[2] / 32;
    int T = E + N;

    float *p_h, *p_xl, *p_xr, *p_wlc, *p_wrc, *p_blc, *p_brc;
    cudaGetSymbolAddress((void**)&p_h,   g_h);
    cudaGetSymbolAddress((void**)&p_xl,  g_xl);
    cudaGetSymbolAddress((void**)&p_xr,  g_xr);
    cudaGetSymbolAddress((void**)&p_wlc, g_wlc);
    cudaGetSymbolAddress((void**)&p_wrc, g_wrc);
    cudaGetSymbolAddress((void**)&p_blc, g_blc);
    cudaGetSymbolAddress((void**)&p_brc, g_brc);

    int gb_n = (N + 127) / 128;
    int nblk = (N + 255) / 256;
    int wb_n = (N * 32 + 255) / 256;

    int lr_smem = LR_SMF * 4;   // 53 KB
    cudaFuncSetAttribute(k_gemm_lr, cudaFuncAttributeMaxDynamicSharedMemorySize, lr_smem);
    cudaFuncSetAttribute(k_escore, cudaFuncAttributeMaxDynamicSharedMemorySize, ESC_SMB);

    // one-time resources (created on the first, non-captured correctness call)
    static cudaStream_t s2 = nullptr;
    static cudaEvent_t  evFork = nullptr, evJoin = nullptr;
    if (s2 == nullptr) {
        cudaStreamCreate(&s2);
        cudaEventCreateWithFlags(&evFork, cudaEventDisableTiming);
        cudaEventCreateWithFlags(&evJoin, cudaEventDisableTiming);
    }

    // ---- fork: CSR build chain on s2, GEMM front-end on the main stream ----
    cudaEventRecord(evFork, 0);
    cudaStreamWaitEvent(s2, evFork, 0);

    // chain B (s2): CSR build + self-loop attrs
    k_detzero<<<nblk, 256, 0, s2>>>(eidx, E, N);
    k_prep<<<(E + 255) / 256, 256, 0, s2>>>(eidx, E);
    k_scan_local<<<nblk, 256, 0, s2>>>(N);
    k_scan_blk<<<1, 256, 0, s2>>>(nblk);
    k_scan_add<<<nblk, 256, 0, s2>>>(N, T);
    k_scatter<<<(T + 255) / 256, 256, 0, s2>>>(E, T);
    k_loopcsr<<<wb_n, 256, 0, s2>>>(ea, E, N);
    cudaEventRecord(evJoin, s2);

    // chain A (main): weight composition + layer-1 node transforms
    k_gemm_tc<<<1, 256>>>(W_emb, Wl[0], nullptr, p_wlc, 128);
    k_gemm_tc<<<1, 256>>>(W_emb, Wr[0], nullptr, p_wrc, 128);
    k_biascomp<<<2, 128>>>(b_emb, Wl[0], bl[0], Wr[0]);
    k_gemm_lr<<<gb_n, 512, lr_smem>>>(x, p_wlc, p_blc, p_wrc, p_brc,
                                      p_xl, p_xr, N);

    // ---- join ----
    cudaStreamWaitEvent(0, evJoin, 0);

    int eb = (T + 127) / 128;
    // layer 1
    k_escore<<<eb, 256, ESC_SMB>>>(ea, We[0], att[0], E, T);
    k_aggr<<<wb_n, 256>>>(bo[0], p_h, E, N);
    // layer 2
    k_gemm_lr<<<gb_n, 512, lr_smem>>>(p_h, Wl[1], bl[1], Wr[1], nullptr,
                                      p_xl, p_xr, N);
    k_escore<<<eb, 256, ESC_SMB>>>(ea, We[1], att[1], E, T);
    k_aggr<<<wb_n, 256>>>(bo[1], (float*)d_out, E, N);
}